// round 3
// baseline (speedup 1.0000x reference)
#include <cuda_runtime.h>
#include <cuda_bf16.h>
#include <math.h>

#define BZ 32
#define SZ 128
#define HZ 768
#define MM 8
#define MH_ 6
#define KK 4

// scratch: per-row dots [B][2][S]  (c=0 -> wt/target, c=1 -> wh/holder)
__device__ float g_dots[BZ * 2 * SZ];

// ---------------------------------------------------------------------------
// Kernel A: per-row dots with wh, wt. grid (BZ, 4) = 128 blocks (~1 wave),
// block 256. Each warp: 4 rows, 24 LDG.128 in flight.
// ---------------------------------------------------------------------------
__global__ __launch_bounds__(256, 1) void k_dots(
    const float* __restrict__ emb,
    const float* __restrict__ wh,
    const float* __restrict__ wt)
{
    const int b = blockIdx.x;
    const int tid = threadIdx.x;
    const int warp = tid >> 5, lane = tid & 31;

    float4 wh4[6], wt4[6];
#pragma unroll
    for (int i = 0; i < 6; i++) {
        wh4[i] = ((const float4*)wh)[lane + 32 * i];
        wt4[i] = ((const float4*)wt)[lane + 32 * i];
    }

    const int r0 = blockIdx.y * 32 + warp * 4;
    const float* eb = emb + ((size_t)b * SZ + r0) * HZ;

    float4 v[4][6];
#pragma unroll
    for (int r = 0; r < 4; r++) {
        const float4* rp = (const float4*)(eb + (size_t)r * HZ);
#pragma unroll
        for (int i = 0; i < 6; i++) v[r][i] = rp[lane + 32 * i];
    }

#pragma unroll
    for (int r = 0; r < 4; r++) {
        float ah = 0.f, at = 0.f;
#pragma unroll
        for (int i = 0; i < 6; i++) {
            ah += v[r][i].x * wh4[i].x + v[r][i].y * wh4[i].y
                + v[r][i].z * wh4[i].z + v[r][i].w * wh4[i].w;
            at += v[r][i].x * wt4[i].x + v[r][i].y * wt4[i].y
                + v[r][i].z * wt4[i].z + v[r][i].w * wt4[i].w;
        }
#pragma unroll
        for (int off = 16; off; off >>= 1) {
            ah += __shfl_xor_sync(0xFFFFFFFFu, ah, off);
            at += __shfl_xor_sync(0xFFFFFFFFu, at, off);
        }
        if (lane == 0) {
            g_dots[b * 2 * SZ + 0 * SZ + (r0 + r)] = at;
            g_dots[b * 2 * SZ + 1 * SZ + (r0 + r)] = ah;
        }
    }
}

// ---------------------------------------------------------------------------
// Kernel B: per-batch prefix sums, scores, top-k, rep dots, logits.
// grid BZ, block 256.
// out layout (floats): implicit[0,512) explicit[512,2560) hs[2560,35328) ts[35328,68096)
// ---------------------------------------------------------------------------
__global__ __launch_bounds__(256, 1) void k_main(
    const float* __restrict__ emb,
    const int* __restrict__ mask,
    const float* __restrict__ bh_,
    const float* __restrict__ bt_,
    const float* __restrict__ wi,
    const float* __restrict__ bi,
    const float* __restrict__ we,
    const float* __restrict__ be,
    float* __restrict__ out)
{
    __shared__ float pref[2][SZ + 1];        // [0]=target(wt), [1]=holder(wh)
    __shared__ float sc[2][MM * SZ];         // [0]=ts, [1]=hs
    __shared__ unsigned long long cand[2][16];
    __shared__ float topv[2][KK];
    __shared__ int   topi[2][KK];
    __shared__ float tdotI[KK][4];
    __shared__ float tdotE[KK][4];
    __shared__ float hdotE[KK][4];
    __shared__ int s_len;

    const int b = blockIdx.x;
    const int tid = threadIdx.x;
    const int warp = tid >> 5, lane = tid & 31;
    const float* eb = emb + (size_t)b * SZ * HZ;

    if (tid == 0) s_len = 0;
    if (tid < 2) pref[tid][0] = 0.f;
    if (tid < 256) {
        int c = tid >> 7, s = tid & 127;
        pref[c][s + 1] = g_dots[b * 2 * SZ + tid];
    }
    __syncthreads();

    // sentence length
    if (tid < SZ) {
        int v = mask[b * SZ + tid];
#pragma unroll
        for (int off = 16; off; off >>= 1) v += __shfl_xor_sync(0xFFFFFFFFu, v, off);
        if (lane == 0) atomicAdd(&s_len, v);
    }
    __syncthreads();

    // prefix sums over S (warps 0,1)
    if (warp < 2) {
        const int c = warp;
        float v0 = pref[c][lane * 4 + 1];
        float v1 = pref[c][lane * 4 + 2];
        float v2 = pref[c][lane * 4 + 3];
        float v3 = pref[c][lane * 4 + 4];
        v1 += v0; v2 += v1; v3 += v2;
        float tot = v3, x = tot;
#pragma unroll
        for (int off = 1; off < 32; off <<= 1) {
            float y = __shfl_up_sync(0xFFFFFFFFu, x, off);
            if (lane >= off) x += y;
        }
        float excl = x - tot;
        pref[c][lane * 4 + 1] = v0 + excl;
        pref[c][lane * 4 + 2] = v1 + excl;
        pref[c][lane * 4 + 3] = v2 + excl;
        pref[c][lane * 4 + 4] = v3 + excl;
    }
    __syncthreads();

    // span scores + hs/ts outputs
    const int len = s_len;
    const float btv = bt_[0], bhv = bh_[0];
    float* out_hs = out + 2560  + (size_t)b * (MM * SZ);
    float* out_ts = out + 35328 + (size_t)b * (MM * SZ);
#pragma unroll
    for (int i = 0; i < 4; i++) {
        int idx = tid + 256 * i;
        int m = idx >> 7, s = idx & 127;
        int e = s + m + 1; if (e > SZ) e = SZ;
        float w = (float)(m + 1);
        bool tv = (s + m) < len;
        bool hv = tv && (m < MH_);
        float dt = (pref[0][e] - pref[0][s]) / w;
        float dh = (pref[1][e] - pref[1][s]) / w;
        float vt = tv ? 1.f / (1.f + expf(-(dt + btv))) : -1.f;
        float vh = hv ? 1.f / (1.f + expf(-(dh + bhv))) : -1.f;
        sc[0][idx] = vt; sc[1][idx] = vh;
        out_ts[idx] = vt; out_hs[idx] = vh;
    }
    __syncthreads();

    // single-pass top-4 (t: warps 0-3, h: warps 4-7)
    {
        const int type = warp >> 2;
        const int base = tid & 127;
        unsigned long long t4[4] = {0ull, 0ull, 0ull, 0ull};
#pragma unroll
        for (int i = 0; i < 8; i++) {
            int idx = base + 128 * i;
            unsigned u = __float_as_uint(sc[type][idx]);
            u = (u & 0x80000000u) ? ~u : (u | 0x80000000u);
            unsigned long long key =
                ((unsigned long long)u << 32) | (unsigned)(0xFFFFFFFFu - idx);
            if (key > t4[0])      { t4[3]=t4[2]; t4[2]=t4[1]; t4[1]=t4[0]; t4[0]=key; }
            else if (key > t4[1]) { t4[3]=t4[2]; t4[2]=t4[1]; t4[1]=key; }
            else if (key > t4[2]) { t4[3]=t4[2]; t4[2]=key; }
            else if (key > t4[3]) { t4[3]=key; }
        }
#pragma unroll
        for (int off = 16; off; off >>= 1) {
            unsigned long long o[4];
#pragma unroll
            for (int j = 0; j < 4; j++) o[j] = __shfl_xor_sync(0xFFFFFFFFu, t4[j], off);
            unsigned long long mrg[4];
            int ai = 0, bi2 = 0;
#pragma unroll
            for (int m = 0; m < 4; m++)
                mrg[m] = (t4[ai] >= o[bi2]) ? t4[ai++] : o[bi2++];
#pragma unroll
            for (int j = 0; j < 4; j++) t4[j] = mrg[j];
        }
        if (lane == 0) {
            int wq = warp & 3;
#pragma unroll
            for (int j = 0; j < 4; j++) cand[type][wq * 4 + j] = t4[j];
        }
    }
    __syncthreads();

    if (lane == 0 && (warp == 0 || warp == 4)) {
        const int type = warp >> 2;
        unsigned long long c16[16];
#pragma unroll
        for (int j = 0; j < 16; j++) c16[j] = cand[type][j];
#pragma unroll
        for (int k = 0; k < KK; k++) {
            unsigned long long best = 0ull; int bj = 0;
#pragma unroll
            for (int j = 0; j < 16; j++)
                if (c16[j] > best) { best = c16[j]; bj = j; }
            c16[bj] = 0ull;
            unsigned hi = (unsigned)(best >> 32);
            unsigned lo = (unsigned)best;
            float v = (hi & 0x80000000u) ? __uint_as_float(hi ^ 0x80000000u)
                                         : __uint_as_float(~hi);
            topv[type][k] = v;
            topi[type][k] = (int)(0xFFFFFFFFu - lo);
        }
    }
    __syncthreads();

    // rep dots for selected spans (1 warp per span; embedding rows are L2-hot)
    {
        const int type = warp >> 2;      // 0 = target, 1 = holder
        const int k = warp & 3;
        const int idx = topi[type][k];
        const bool valid = topv[type][k] > 0.f;
        const int m = idx >> 7, s = idx & 127;
        const float inv = 1.f / (float)(m + 1);
        float acc[8] = {0.f,0.f,0.f,0.f,0.f,0.f,0.f,0.f};
        if (valid) {
#pragma unroll 1
            for (int i = 0; i < 6; i++) {
                int h4 = lane + 32 * i;
                float4 sum = make_float4(0.f, 0.f, 0.f, 0.f);
                for (int r = 0; r <= m; r++) {
                    float4 v = ((const float4*)(eb + (size_t)(s + r) * HZ))[h4];
                    sum.x += v.x; sum.y += v.y; sum.z += v.z; sum.w += v.w;
                }
                sum.x *= inv; sum.y *= inv; sum.z *= inv; sum.w *= inv;
                const float* sp = &sum.x;
                if (type == 0) {
#pragma unroll
                    for (int c = 0; c < 4; c++) {
                        float sv = sp[c];
                        float4 wv = ((const float4*)wi)[4 * h4 + c];
                        acc[0] += sv * wv.x; acc[1] += sv * wv.y;
                        acc[2] += sv * wv.z; acc[3] += sv * wv.w;
                        float4 ev = ((const float4*)we)[HZ + 4 * h4 + c];
                        acc[4] += sv * ev.x; acc[5] += sv * ev.y;
                        acc[6] += sv * ev.z; acc[7] += sv * ev.w;
                    }
                } else {
#pragma unroll
                    for (int c = 0; c < 4; c++) {
                        float sv = sp[c];
                        float4 ev = ((const float4*)we)[4 * h4 + c];
                        acc[0] += sv * ev.x; acc[1] += sv * ev.y;
                        acc[2] += sv * ev.z; acc[3] += sv * ev.w;
                    }
                }
            }
        }
#pragma unroll
        for (int j = 0; j < 8; j++)
#pragma unroll
            for (int off = 16; off; off >>= 1)
                acc[j] += __shfl_xor_sync(0xFFFFFFFFu, acc[j], off);
        if (lane == 0) {
            if (type == 0) {
#pragma unroll
                for (int j = 0; j < 4; j++) { tdotI[k][j] = acc[j]; tdotE[k][j] = acc[4 + j]; }
            } else {
#pragma unroll
                for (int j = 0; j < 4; j++) hdotE[k][j] = acc[j];
            }
        }
    }
    __syncthreads();

    // logits
    if (tid < 64) {
        int k = tid >> 4, i = (tid >> 2) & 3, j = tid & 3;
        bool pv = (topv[1][k] > 0.f) && (topv[0][i] > 0.f);
        float val = be[j] + (pv ? (hdotE[k][j] + tdotE[i][j]) : 0.f);
        out[512 + (size_t)b * 64 + tid] = val;
    } else if (tid < 80) {
        int t2 = tid - 64;
        int i = t2 >> 2, j = t2 & 3;
        float val = bi[j] + ((topv[0][i] > 0.f) ? tdotI[i][j] : 0.f);
        out[(size_t)b * 16 + t2] = val;
    }
}

extern "C" void kernel_launch(void* const* d_in, const int* in_sizes, int n_in,
                              void* d_out, int out_size)
{
    const float* emb = (const float*)d_in[0];
    const int*   msk = (const int*)d_in[1];
    const float* wh  = (const float*)d_in[2];
    const float* bh  = (const float*)d_in[3];
    const float* wt  = (const float*)d_in[4];
    const float* bt  = (const float*)d_in[5];
    const float* wi  = (const float*)d_in[6];
    const float* bi  = (const float*)d_in[7];
    const float* we  = (const float*)d_in[8];
    const float* be  = (const float*)d_in[9];
    float* out = (float*)d_out;

    dim3 gA(BZ, 4, 1);
    k_dots<<<gA, 256>>>(emb, wh, wt);
    k_main<<<BZ, 256>>>(emb, msk, bh, bt, wi, bi, we, be, out);
}

// round 4
// speedup vs baseline: 1.0152x; 1.0152x over previous
#include <cuda_runtime.h>
#include <cuda_bf16.h>
#include <math.h>

#define BZ 32
#define SZ 128
#define HZ 768
#define MM 8
#define MH_ 6
#define KK 4

__device__ float g_dots[BZ * 2 * SZ];  // [B][2][S]: c=0 target(wt), c=1 holder(wh)
__constant__ float c_inv[8] = {1.f, 1.f/2.f, 1.f/3.f, 1.f/4.f, 1.f/5.f, 1.f/6.f, 1.f/7.f, 1.f/8.f};

// compare-exchange descending on u64 keys
#define CE(x, y) { unsigned long long _a = (x), _b = (y); (x) = _a > _b ? _a : _b; (y) = _a > _b ? _b : _a; }

// ---------------------------------------------------------------------------
// Kernel A: per-row wh/wt dots. grid (BZ,4)=128 blocks, 256 thr, 4 rows/warp.
// ---------------------------------------------------------------------------
__global__ __launch_bounds__(256, 1) void k_dots(
    const float* __restrict__ emb,
    const float* __restrict__ wh,
    const float* __restrict__ wt)
{
    const int b = blockIdx.x;
    const int tid = threadIdx.x;
    const int warp = tid >> 5, lane = tid & 31;

    float4 wh4[6], wt4[6];
#pragma unroll
    for (int i = 0; i < 6; i++) {
        wh4[i] = ((const float4*)wh)[lane + 32 * i];
        wt4[i] = ((const float4*)wt)[lane + 32 * i];
    }

    const int r0 = blockIdx.y * 32 + warp * 4;
    const float* eb = emb + ((size_t)b * SZ + r0) * HZ;

    float4 v[4][6];
#pragma unroll
    for (int r = 0; r < 4; r++) {
        const float4* rp = (const float4*)(eb + (size_t)r * HZ);
#pragma unroll
        for (int i = 0; i < 6; i++) v[r][i] = rp[lane + 32 * i];
    }
#pragma unroll
    for (int r = 0; r < 4; r++) {
        float ah = 0.f, at = 0.f;
#pragma unroll
        for (int i = 0; i < 6; i++) {
            ah += v[r][i].x * wh4[i].x + v[r][i].y * wh4[i].y
                + v[r][i].z * wh4[i].z + v[r][i].w * wh4[i].w;
            at += v[r][i].x * wt4[i].x + v[r][i].y * wt4[i].y
                + v[r][i].z * wt4[i].z + v[r][i].w * wt4[i].w;
        }
#pragma unroll
        for (int off = 16; off; off >>= 1) {
            ah += __shfl_xor_sync(0xFFFFFFFFu, ah, off);
            at += __shfl_xor_sync(0xFFFFFFFFu, at, off);
        }
        if (lane == 0) {
            g_dots[b * 2 * SZ + (r0 + r)]      = at;
            g_dots[b * 2 * SZ + SZ + (r0 + r)] = ah;
        }
    }
}

// ---------------------------------------------------------------------------
// Kernel B: per-batch everything else. grid BZ, block 512.
// out layout (floats): implicit[0,512) explicit[512,2560) hs[2560,35328) ts[35328,68096)
// ---------------------------------------------------------------------------
__global__ __launch_bounds__(512, 1) void k_main(
    const float* __restrict__ emb,
    const int* __restrict__ mask,
    const float* __restrict__ bh_,
    const float* __restrict__ bt_,
    const float* __restrict__ wi,
    const float* __restrict__ bi,
    const float* __restrict__ we,
    const float* __restrict__ be,
    float* __restrict__ out)
{
    __shared__ float swi[HZ * 4];        // 12 KB: wi[H][4]
    __shared__ float swe[2 * HZ * 4];    // 24 KB: we[2H][4]
    __shared__ float pref[2][SZ + 1];
    __shared__ float sc[2][MM * SZ];
    __shared__ unsigned long long cand[2][32];
    __shared__ float topv[2][KK];
    __shared__ int   topi[2][KK];
    __shared__ float partial[16][8];
    __shared__ float sbias[10];          // 0:bh 1:bt 2-5:bi 6-9:be
    __shared__ int s_len;

    const int b = blockIdx.x;
    const int tid = threadIdx.x;
    const int warp = tid >> 5, lane = tid & 31;
    const float* eb = emb + (size_t)b * SZ * HZ;

    // ---- prefetch weights & biases into smem (latency overlapped with phases 1-4)
    {
        float4* swi4 = (float4*)swi;
        float4* swe4 = (float4*)swe;
        const float4* wi4 = (const float4*)wi;
        const float4* we4 = (const float4*)we;
#pragma unroll
        for (int i = 0; i < 5; i++) {
            int j = tid + 512 * i;
            if (j < 768)       swi4[j] = wi4[j];
            else if (j < 2304) swe4[j - 768] = we4[j - 768];
        }
        if (tid == 0) { sbias[0] = bh_[0]; sbias[1] = bt_[0]; s_len = 0; }
        else if (tid >= 2 && tid < 6)  sbias[tid]     = bi[tid - 2];
        else if (tid >= 6 && tid < 10) sbias[tid]     = be[tid - 6];
    }

    // ---- load per-row dots + mask length
    if (tid < 256) pref[tid >> 7][(tid & 127) + 1] = g_dots[b * 2 * SZ + tid];
    if (tid < 2) pref[tid][0] = 0.f;
    if (tid < SZ) {
        int v = mask[b * SZ + tid];
#pragma unroll
        for (int off = 16; off; off >>= 1) v += __shfl_xor_sync(0xFFFFFFFFu, v, off);
        if (lane == 0) atomicAdd(&s_len, v);
    }
    __syncthreads();

    // ---- prefix sums over S (warps 0,1)
    if (warp < 2) {
        const int c = warp;
        float v0 = pref[c][lane * 4 + 1];
        float v1 = pref[c][lane * 4 + 2];
        float v2 = pref[c][lane * 4 + 3];
        float v3 = pref[c][lane * 4 + 4];
        v1 += v0; v2 += v1; v3 += v2;
        float tot = v3, x = tot;
#pragma unroll
        for (int off = 1; off < 32; off <<= 1) {
            float y = __shfl_up_sync(0xFFFFFFFFu, x, off);
            if (lane >= off) x += y;
        }
        float excl = x - tot;
        pref[c][lane * 4 + 1] = v0 + excl;
        pref[c][lane * 4 + 2] = v1 + excl;
        pref[c][lane * 4 + 3] = v2 + excl;
        pref[c][lane * 4 + 4] = v3 + excl;
    }
    __syncthreads();

    // ---- span scores + hs/ts outputs (2 per thread)
    const int len = s_len;
    const float bhv = sbias[0], btv = sbias[1];
    float* out_hs = out + 2560  + (size_t)b * (MM * SZ);
    float* out_ts = out + 35328 + (size_t)b * (MM * SZ);
#pragma unroll
    for (int i = 0; i < 2; i++) {
        int idx = tid + 512 * i;
        int m = idx >> 7, s = idx & 127;
        int e = s + m + 1; if (e > SZ) e = SZ;
        float invw = c_inv[m];
        bool tv = (s + m) < len;
        bool hv = tv && (m < MH_);
        float dt = (pref[0][e] - pref[0][s]) * invw;
        float dh = (pref[1][e] - pref[1][s]) * invw;
        float vt = tv ? 1.f / (1.f + __expf(-(dt + btv))) : -1.f;
        float vh = hv ? 1.f / (1.f + __expf(-(dh + bhv))) : -1.f;
        sc[0][idx] = vt; sc[1][idx] = vh;
        out_ts[idx] = vt; out_hs[idx] = vh;
    }
    __syncthreads();

    // ---- top-4 (t: warps 0-7, h: warps 8-15), branchless bitonic networks
    {
        const int type = warp >> 3;
        const int base = tid & 255;
        unsigned long long k0, k1, k2, k3;
        {
            unsigned long long kk[4];
#pragma unroll
            for (int i = 0; i < 4; i++) {
                int idx = base + 256 * i;
                unsigned u = __float_as_uint(sc[type][idx]);
                u = (u & 0x80000000u) ? ~u : (u | 0x80000000u);
                kk[i] = ((unsigned long long)u << 32) | (unsigned)(0xFFFFFFFFu - idx);
            }
            k0 = kk[0]; k1 = kk[1]; k2 = kk[2]; k3 = kk[3];
        }
        // sort4 descending: CE(0,1), CE(3,2) -> bitonic; halve; cleanup
        CE(k0, k1); CE(k3, k2);
        CE(k0, k2); CE(k1, k3);
        CE(k0, k1); CE(k2, k3);
        // butterfly merge of sorted-4 lists (keep top-4)
#pragma unroll
        for (int off = 16; off; off >>= 1) {
            unsigned long long o0 = __shfl_xor_sync(0xFFFFFFFFu, k0, off);
            unsigned long long o1 = __shfl_xor_sync(0xFFFFFFFFu, k1, off);
            unsigned long long o2 = __shfl_xor_sync(0xFFFFFFFFu, k2, off);
            unsigned long long o3 = __shfl_xor_sync(0xFFFFFFFFu, k3, off);
            unsigned long long c0 = k0 > o3 ? k0 : o3;
            unsigned long long c1 = k1 > o2 ? k1 : o2;
            unsigned long long c2 = k2 > o1 ? k2 : o1;
            unsigned long long c3 = k3 > o0 ? k3 : o0;
            // bitonic cleanup (desc)
            CE(c0, c2); CE(c1, c3);
            CE(c0, c1); CE(c2, c3);
            k0 = c0; k1 = c1; k2 = c2; k3 = c3;
        }
        if (lane == 0) {
            int wq = warp & 7;
            cand[type][wq * 4 + 0] = k0;
            cand[type][wq * 4 + 1] = k1;
            cand[type][wq * 4 + 2] = k2;
            cand[type][wq * 4 + 3] = k3;
        }
    }
    __syncthreads();

    // ---- final selection: one full warp per type over 32 candidates
    if (warp == 0 || warp == 8) {
        const int type = warp >> 3;
        unsigned long long key = cand[type][lane];
#pragma unroll
        for (int k = 0; k < KK; k++) {
            unsigned long long red = key;
#pragma unroll
            for (int off = 16; off; off >>= 1) {
                unsigned long long o = __shfl_xor_sync(0xFFFFFFFFu, red, off);
                red = o > red ? o : red;
            }
            if (key == red) key = 0ull;   // remove winner (keys unique)
            if (lane == 0) {
                unsigned hi = (unsigned)(red >> 32);
                unsigned lo = (unsigned)red;
                float v = (hi & 0x80000000u) ? __uint_as_float(hi ^ 0x80000000u)
                                             : __uint_as_float(~hi);
                topv[type][k] = v;
                topi[type][k] = (int)(0xFFFFFFFFu - lo);
            }
        }
    }
    __syncthreads();

    // ---- rep dots for selected spans: 2 warps per span (16 warps total)
    {
        const int type = warp >> 3;          // 0=target, 1=holder
        const int span = (warp >> 1) & 3;
        const int half = warp & 1;
        const int idx = topi[type][span];
        const bool valid = topv[type][span] > 0.f;
        const int m = idx >> 7, s = idx & 127;
        const float invw = c_inv[m];

        float4 sum0 = make_float4(0.f,0.f,0.f,0.f);
        float4 sum1 = sum0, sum2 = sum0;
        if (valid) {
            const int c0i = lane + 96 * half;
#pragma unroll
            for (int r = 0; r < 8; r++) {
                if (r <= m) {
                    const float4* rp = (const float4*)(eb + (size_t)(s + r) * HZ);
                    float4 a = rp[c0i], bb = rp[c0i + 32], cc = rp[c0i + 64];
                    sum0.x += a.x;  sum0.y += a.y;  sum0.z += a.z;  sum0.w += a.w;
                    sum1.x += bb.x; sum1.y += bb.y; sum1.z += bb.z; sum1.w += bb.w;
                    sum2.x += cc.x; sum2.y += cc.y; sum2.z += cc.z; sum2.w += cc.w;
                }
            }
        }
        float acc[8] = {0.f,0.f,0.f,0.f,0.f,0.f,0.f,0.f};
        if (valid) {
            const float4* swi4 = (const float4*)swi;
            const float4* swe4 = (const float4*)swe;
            float4 sums[3] = {sum0, sum1, sum2};
#pragma unroll
            for (int c = 0; c < 3; c++) {
                int h4 = lane + 96 * half + 32 * c;
                float sv[4] = {sums[c].x * invw, sums[c].y * invw,
                               sums[c].z * invw, sums[c].w * invw};
#pragma unroll
                for (int j = 0; j < 4; j++) {
                    int f = 4 * h4 + j;
                    if (type == 0) {
                        float4 wv = swi4[f];
                        acc[0] += sv[j] * wv.x; acc[1] += sv[j] * wv.y;
                        acc[2] += sv[j] * wv.z; acc[3] += sv[j] * wv.w;
                        float4 ev = swe4[HZ + f];
                        acc[4] += sv[j] * ev.x; acc[5] += sv[j] * ev.y;
                        acc[6] += sv[j] * ev.z; acc[7] += sv[j] * ev.w;
                    } else {
                        float4 ev = swe4[f];
                        acc[0] += sv[j] * ev.x; acc[1] += sv[j] * ev.y;
                        acc[2] += sv[j] * ev.z; acc[3] += sv[j] * ev.w;
                    }
                }
            }
        }
#pragma unroll
        for (int j = 0; j < 8; j++)
#pragma unroll
            for (int off = 16; off; off >>= 1)
                acc[j] += __shfl_xor_sync(0xFFFFFFFFu, acc[j], off);
        if (lane == 0) {
#pragma unroll
            for (int j = 0; j < 8; j++) partial[warp][j] = acc[j];
        }
    }
    __syncthreads();

    // ---- logits
    if (tid < 64) {
        int k = tid >> 4, i = (tid >> 2) & 3, j = tid & 3;
        bool pv = (topv[1][k] > 0.f) && (topv[0][i] > 0.f);
        float val = sbias[6 + j];
        if (pv) val += partial[8 + 2*k][j] + partial[9 + 2*k][j]
                     + partial[2*i][4 + j] + partial[2*i + 1][4 + j];
        out[512 + (size_t)b * 64 + tid] = val;
    } else if (tid < 80) {
        int t2 = tid - 64;
        int i = t2 >> 2, j = t2 & 3;
        float val = sbias[2 + j];
        if (topv[0][i] > 0.f) val += partial[2*i][j] + partial[2*i + 1][j];
        out[(size_t)b * 16 + t2] = val;
    }
}

extern "C" void kernel_launch(void* const* d_in, const int* in_sizes, int n_in,
                              void* d_out, int out_size)
{
    const float* emb = (const float*)d_in[0];
    const int*   msk = (const int*)d_in[1];
    const float* wh  = (const float*)d_in[2];
    const float* bh  = (const float*)d_in[3];
    const float* wt  = (const float*)d_in[4];
    const float* bt  = (const float*)d_in[5];
    const float* wi  = (const float*)d_in[6];
    const float* bi  = (const float*)d_in[7];
    const float* we  = (const float*)d_in[8];
    const float* be  = (const float*)d_in[9];
    float* out = (float*)d_out;

    dim3 gA(BZ, 4, 1);
    k_dots<<<gA, 256>>>(emb, wh, wt);
    k_main<<<BZ, 512>>>(emb, msk, bh, bt, wi, bi, we, be, out);
}